// round 1
// baseline (speedup 1.0000x reference)
#include <cuda_runtime.h>
#include <math.h>

#define T_TOK 4096
#define DM    1024
#define DFF   2048
#define DFF2  4096
#define NEXP  8

#define BM 128
#define BN 128
#define BK 16

// -------- scratch (no allocations allowed; static device globals) --------
__device__ int   g_counts[NEXP];
__device__ int   g_slots[NEXP * T_TOK];     // slot = token*2 + k
__device__ float g_gate_s[NEXP * T_TOK];
__device__ int   g_top_idx[T_TOK * 2];
__device__ float g_top_gate[T_TOK * 2];
__device__ float g_h  [(size_t)(2 * T_TOK) * DFF2];  // 8192 x 4096 (128 MB)
__device__ float g_act[(size_t)(2 * T_TOK) * DFF];   // 8192 x 2048 ( 64 MB)

// -------- zero output + expert counts --------
__global__ void zero_kernel(float* __restrict__ out) {
    int i = blockIdx.x * blockDim.x + threadIdx.x;   // one float4 each
    float4 z = make_float4(0.f, 0.f, 0.f, 0.f);
    ((float4*)out)[i] = z;
    if (blockIdx.x == 0 && threadIdx.x < NEXP) g_counts[threadIdx.x] = 0;
}

// -------- router: logits, top-2, softmax gates --------
__global__ void __launch_bounds__(256) router_kernel(
        const float* __restrict__ x, const float* __restrict__ rw,
        float* __restrict__ logits) {
    int t = blockIdx.x;
    int tid = threadIdx.x;
    const float* xr = x + (size_t)t * DM;
    float acc[NEXP];
#pragma unroll
    for (int e = 0; e < NEXP; e++) acc[e] = 0.f;
    for (int i = tid; i < DM; i += 256) {
        float xv = xr[i];
#pragma unroll
        for (int e = 0; e < NEXP; e++) acc[e] += xv * rw[e * DM + i];
    }
    __shared__ float red[NEXP][256];
    __shared__ float fin[NEXP];
#pragma unroll
    for (int e = 0; e < NEXP; e++) red[e][tid] = acc[e];
    __syncthreads();
    int w = tid >> 5, lane = tid & 31;
    if (w < NEXP) {
        float s = 0.f;
#pragma unroll
        for (int j = 0; j < 256; j += 32) s += red[w][lane + j];
#pragma unroll
        for (int o = 16; o > 0; o >>= 1) s += __shfl_down_sync(0xffffffffu, s, o);
        if (lane == 0) { fin[w] = s; logits[(size_t)t * NEXP + w] = s; }
    }
    __syncthreads();
    if (tid == 0) {
        int i0 = 0; float v0 = fin[0];
#pragma unroll
        for (int e = 1; e < NEXP; e++) if (fin[e] > v0) { v0 = fin[e]; i0 = e; }
        int i1 = -1; float v1 = -3.4e38f;
#pragma unroll
        for (int e = 0; e < NEXP; e++) if (e != i0 && fin[e] > v1) { v1 = fin[e]; i1 = e; }
        float e1 = expf(v1 - v0);         // <= 1
        float inv = 1.f / (1.f + e1);
        g_top_idx[t * 2 + 0] = i0;  g_top_gate[t * 2 + 0] = inv;
        g_top_idx[t * 2 + 1] = i1;  g_top_gate[t * 2 + 1] = e1 * inv;
    }
}

// -------- bin assignments per expert --------
__global__ void bin_kernel() {
    int i = blockIdx.x * blockDim.x + threadIdx.x;
    if (i >= T_TOK * 2) return;
    int e = g_top_idx[i];
    int p = atomicAdd(&g_counts[e], 1);
    g_slots[e * T_TOK + p]  = i;
    g_gate_s[e * T_TOK + p] = g_top_gate[i];
}

// -------- grouped GEMM1: h[slot] = x[token] @ w_in[e]^T  (M=cnt, N=4096, K=1024) --------
__global__ void __launch_bounds__(256) gemm1_kernel(
        const float* __restrict__ x, const float* __restrict__ w_in) {
    int e = blockIdx.z;
    int cnt = g_counts[e];
    int m0 = blockIdx.y * BM;
    if (m0 >= cnt) return;
    int n0 = blockIdx.x * BN;
    const float* B = w_in + (size_t)e * DFF2 * DM;

    __shared__ float As[BK][BM];
    __shared__ float Bs[BK][BN];
    __shared__ int   rs[BM];
    int tid = threadIdx.x;
    if (tid < BM) {
        int m = m0 + tid;
        rs[tid] = (m < cnt) ? g_slots[e * T_TOK + m] : -1;
    }
    __syncthreads();

    int lrow = tid >> 1;
    int lc   = (tid & 1) * 8;
    int slot = rs[lrow];
    const float* aptr = (slot >= 0) ? (x + (size_t)(slot >> 1) * DM + lc) : x;
    const float* bptr = B + (size_t)(n0 + lrow) * DM + lc;

    int ty = tid >> 4, tx = tid & 15;
    float c[8][8];
#pragma unroll
    for (int i = 0; i < 8; i++)
#pragma unroll
        for (int j = 0; j < 8; j++) c[i][j] = 0.f;

    for (int k0 = 0; k0 < DM; k0 += BK) {
        float4 a0, a1, b0, b1;
        if (slot >= 0) {
            a0 = *(const float4*)(aptr + k0);
            a1 = *(const float4*)(aptr + k0 + 4);
        } else { a0 = make_float4(0,0,0,0); a1 = a0; }
        b0 = *(const float4*)(bptr + k0);
        b1 = *(const float4*)(bptr + k0 + 4);
        __syncthreads();
        As[lc+0][lrow]=a0.x; As[lc+1][lrow]=a0.y; As[lc+2][lrow]=a0.z; As[lc+3][lrow]=a0.w;
        As[lc+4][lrow]=a1.x; As[lc+5][lrow]=a1.y; As[lc+6][lrow]=a1.z; As[lc+7][lrow]=a1.w;
        Bs[lc+0][lrow]=b0.x; Bs[lc+1][lrow]=b0.y; Bs[lc+2][lrow]=b0.z; Bs[lc+3][lrow]=b0.w;
        Bs[lc+4][lrow]=b1.x; Bs[lc+5][lrow]=b1.y; Bs[lc+6][lrow]=b1.z; Bs[lc+7][lrow]=b1.w;
        __syncthreads();
#pragma unroll
        for (int kk = 0; kk < BK; kk++) {
            float4 av0 = *(const float4*)&As[kk][ty * 8];
            float4 av1 = *(const float4*)&As[kk][ty * 8 + 4];
            float4 bv0 = *(const float4*)&Bs[kk][tx * 8];
            float4 bv1 = *(const float4*)&Bs[kk][tx * 8 + 4];
            float a[8] = {av0.x, av0.y, av0.z, av0.w, av1.x, av1.y, av1.z, av1.w};
            float b[8] = {bv0.x, bv0.y, bv0.z, bv0.w, bv1.x, bv1.y, bv1.z, bv1.w};
#pragma unroll
            for (int i = 0; i < 8; i++)
#pragma unroll
                for (int j = 0; j < 8; j++) c[i][j] += a[i] * b[j];
        }
    }
#pragma unroll
    for (int i = 0; i < 8; i++) {
        int m = ty * 8 + i;
        int s = rs[m];
        if (s >= 0) {
            float* hp = g_h + (size_t)s * DFF2 + n0 + tx * 8;
            *(float4*)(hp)     = make_float4(c[i][0], c[i][1], c[i][2], c[i][3]);
            *(float4*)(hp + 4) = make_float4(c[i][4], c[i][5], c[i][6], c[i][7]);
        }
    }
}

// -------- SwiGLU: act = silu(h1) * h2 --------
__global__ void swiglu_kernel() {
    size_t i = (size_t)blockIdx.x * blockDim.x + threadIdx.x;   // float4 idx into act
    size_t r = i >> 9;                 // 512 float4 per act row
    size_t f = (i & 511) << 2;
    float4 h1 = *(const float4*)(g_h + r * DFF2 + f);
    float4 h2 = *(const float4*)(g_h + r * DFF2 + DFF + f);
    float4 o;
    o.x = h1.x / (1.f + expf(-h1.x)) * h2.x;
    o.y = h1.y / (1.f + expf(-h1.y)) * h2.y;
    o.z = h1.z / (1.f + expf(-h1.z)) * h2.z;
    o.w = h1.w / (1.f + expf(-h1.w)) * h2.w;
    *(float4*)(g_act + r * DFF + f) = o;
}

// -------- grouped GEMM2: out[token] += gate * (act[slot] @ w_out[e]^T)  (N=1024, K=2048) --------
__global__ void __launch_bounds__(256) gemm2_kernel(
        const float* __restrict__ w_out, float* __restrict__ out) {
    int e = blockIdx.z;
    int cnt = g_counts[e];
    int m0 = blockIdx.y * BM;
    if (m0 >= cnt) return;
    int n0 = blockIdx.x * BN;
    const float* B = w_out + (size_t)e * DM * DFF;

    __shared__ float As[BK][BM];
    __shared__ float Bs[BK][BN];
    __shared__ int   rs[BM];
    __shared__ float gv[BM];
    int tid = threadIdx.x;
    if (tid < BM) {
        int m = m0 + tid;
        rs[tid] = (m < cnt) ? g_slots[e * T_TOK + m] : -1;
        gv[tid] = (m < cnt) ? g_gate_s[e * T_TOK + m] : 0.f;
    }
    __syncthreads();

    int lrow = tid >> 1;
    int lc   = (tid & 1) * 8;
    int slot = rs[lrow];
    const float* aptr = (slot >= 0) ? (g_act + (size_t)slot * DFF + lc) : g_act;
    const float* bptr = B + (size_t)(n0 + lrow) * DFF + lc;

    int ty = tid >> 4, tx = tid & 15;
    float c[8][8];
#pragma unroll
    for (int i = 0; i < 8; i++)
#pragma unroll
        for (int j = 0; j < 8; j++) c[i][j] = 0.f;

    for (int k0 = 0; k0 < DFF; k0 += BK) {
        float4 a0, a1, b0, b1;
        if (slot >= 0) {
            a0 = *(const float4*)(aptr + k0);
            a1 = *(const float4*)(aptr + k0 + 4);
        } else { a0 = make_float4(0,0,0,0); a1 = a0; }
        b0 = *(const float4*)(bptr + k0);
        b1 = *(const float4*)(bptr + k0 + 4);
        __syncthreads();
        As[lc+0][lrow]=a0.x; As[lc+1][lrow]=a0.y; As[lc+2][lrow]=a0.z; As[lc+3][lrow]=a0.w;
        As[lc+4][lrow]=a1.x; As[lc+5][lrow]=a1.y; As[lc+6][lrow]=a1.z; As[lc+7][lrow]=a1.w;
        Bs[lc+0][lrow]=b0.x; Bs[lc+1][lrow]=b0.y; Bs[lc+2][lrow]=b0.z; Bs[lc+3][lrow]=b0.w;
        Bs[lc+4][lrow]=b1.x; Bs[lc+5][lrow]=b1.y; Bs[lc+6][lrow]=b1.z; Bs[lc+7][lrow]=b1.w;
        __syncthreads();
#pragma unroll
        for (int kk = 0; kk < BK; kk++) {
            float4 av0 = *(const float4*)&As[kk][ty * 8];
            float4 av1 = *(const float4*)&As[kk][ty * 8 + 4];
            float4 bv0 = *(const float4*)&Bs[kk][tx * 8];
            float4 bv1 = *(const float4*)&Bs[kk][tx * 8 + 4];
            float a[8] = {av0.x, av0.y, av0.z, av0.w, av1.x, av1.y, av1.z, av1.w};
            float b[8] = {bv0.x, bv0.y, bv0.z, bv0.w, bv1.x, bv1.y, bv1.z, bv1.w};
#pragma unroll
            for (int i = 0; i < 8; i++)
#pragma unroll
                for (int j = 0; j < 8; j++) c[i][j] += a[i] * b[j];
        }
    }
#pragma unroll
    for (int i = 0; i < 8; i++) {
        int m = ty * 8 + i;
        int s = rs[m];
        if (s >= 0) {
            float g = gv[m];
            int tok = s >> 1;
            float* op = out + (size_t)tok * DM + n0 + tx * 8;
#pragma unroll
            for (int j = 0; j < 8; j++) atomicAdd(op + j, g * c[i][j]);
        }
    }
}

extern "C" void kernel_launch(void* const* d_in, const int* in_sizes, int n_in,
                              void* d_out, int out_size) {
    const float* x    = (const float*)d_in[0];   // [4096, 1024]
    const float* rw   = (const float*)d_in[1];   // [8, 1024]
    const float* w_in = (const float*)d_in[2];   // [8, 4096, 1024]
    const float* wout = (const float*)d_in[3];   // [8, 1024, 2048]
    float* out    = (float*)d_out;               // [4096, 1024]
    float* logits = out + (size_t)T_TOK * DM;    // [4096, 8]

    zero_kernel<<<(T_TOK * DM / 4) / 256, 256>>>(out);
    router_kernel<<<T_TOK, 256>>>(x, rw, logits);
    bin_kernel<<<(T_TOK * 2 + 255) / 256, 256>>>();
    gemm1_kernel<<<dim3(DFF2 / BN, T_TOK / BM, NEXP), 256>>>(x, w_in);
    swiglu_kernel<<<((size_t)2 * T_TOK * DFF / 4) / 256, 256>>>();
    gemm2_kernel<<<dim3(DM / BN, T_TOK / BM, NEXP), 256>>>(wout, out);
}

// round 3
// speedup vs baseline: 2.3727x; 2.3727x over previous
#include <cuda_runtime.h>
#include <math.h>
#include <stdint.h>

#define T_TOK 4096
#define DM    1024
#define DFF   2048
#define DFF2  4096
#define NEXP  8
#define KC    32
#define NCH1  (DM/KC)     // 32
#define NCH2  (DFF/KC)    // 64

// ---------------- scratch ----------------
__device__ int   g_counts[NEXP];
__device__ int   g_slots[NEXP * T_TOK];
__device__ int   g_top_idx[T_TOK * 2];
__device__ float g_top_gate[T_TOK * 2];
__device__ float g_xr [(size_t)T_TOK * DM];          // tf32-rounded x
__device__ float g_w1r[(size_t)NEXP * DFF2 * DM];    // tf32-rounded w_in
__device__ float g_w2r[(size_t)NEXP * DM * DFF];     // tf32-rounded w_out
__device__ float g_act[(size_t)2 * T_TOK * DFF];     // swiglu output (tf32-rounded)
__device__ float g_y  [(size_t)2 * T_TOK * DM];      // per-slot gemm2 output

// ---------------- helpers ----------------
static __device__ __forceinline__ uint32_t smem_u32(const void* p) {
    uint32_t a;
    asm("{ .reg .u64 t; cvta.to.shared.u64 t, %1; cvt.u32.u64 %0, t; }" : "=r"(a) : "l"(p));
    return a;
}
static __device__ __forceinline__ void cp16(uint32_t d, const void* s) {
    asm volatile("cp.async.cg.shared.global [%0], [%1], 16;" :: "r"(d), "l"(s) : "memory");
}
#define CP_COMMIT() asm volatile("cp.async.commit_group;" ::: "memory")

static __device__ __forceinline__ uint32_t tf32_rna(float x) {
    uint32_t o;
    asm("cvt.rna.tf32.f32 %0, %1;" : "=r"(o) : "f"(x));
    return o;
}

static __device__ __forceinline__ void mma_tf32(float* c,
        uint32_t a0, uint32_t a1, uint32_t a2, uint32_t a3,
        uint32_t b0, uint32_t b1) {
    asm volatile(
        "mma.sync.aligned.m16n8k8.row.col.f32.tf32.tf32.f32 "
        "{%0, %1, %2, %3}, {%4, %5, %6, %7}, {%8, %9}, {%0, %1, %2, %3};"
        : "+f"(c[0]), "+f"(c[1]), "+f"(c[2]), "+f"(c[3])
        : "r"(a0), "r"(a1), "r"(a2), "r"(a3), "r"(b0), "r"(b1));
}

// ---------------- small kernels ----------------
__global__ void init_kernel() {
    if (threadIdx.x < NEXP) g_counts[threadIdx.x] = 0;
}

__global__ void __launch_bounds__(256) round_kernel(const float4* __restrict__ s,
                                                    float4* __restrict__ d, int n4) {
    int i = blockIdx.x * 256 + threadIdx.x;
    if (i >= n4) return;
    float4 v = s[i];
    float4 o;
    o.x = __uint_as_float(tf32_rna(v.x));
    o.y = __uint_as_float(tf32_rna(v.y));
    o.z = __uint_as_float(tf32_rna(v.z));
    o.w = __uint_as_float(tf32_rna(v.w));
    d[i] = o;
}

__global__ void __launch_bounds__(256) router_kernel(
        const float* __restrict__ x, const float* __restrict__ rw,
        float* __restrict__ logits) {
    int t = blockIdx.x;
    int tid = threadIdx.x;
    const float* xr = x + (size_t)t * DM;
    float acc[NEXP];
#pragma unroll
    for (int e = 0; e < NEXP; e++) acc[e] = 0.f;
    for (int i = tid; i < DM; i += 256) {
        float xv = xr[i];
#pragma unroll
        for (int e = 0; e < NEXP; e++) acc[e] += xv * rw[e * DM + i];
    }
    __shared__ float red[NEXP][256];
    __shared__ float fin[NEXP];
#pragma unroll
    for (int e = 0; e < NEXP; e++) red[e][tid] = acc[e];
    __syncthreads();
    int w = tid >> 5, lane = tid & 31;
    if (w < NEXP) {
        float s = 0.f;
#pragma unroll
        for (int j = 0; j < 256; j += 32) s += red[w][lane + j];
#pragma unroll
        for (int o = 16; o > 0; o >>= 1) s += __shfl_down_sync(0xffffffffu, s, o);
        if (lane == 0) { fin[w] = s; logits[(size_t)t * NEXP + w] = s; }
    }
    __syncthreads();
    if (tid == 0) {
        int i0 = 0; float v0 = fin[0];
#pragma unroll
        for (int e = 1; e < NEXP; e++) if (fin[e] > v0) { v0 = fin[e]; i0 = e; }
        int i1 = -1; float v1 = -3.4e38f;
#pragma unroll
        for (int e = 0; e < NEXP; e++) if (e != i0 && fin[e] > v1) { v1 = fin[e]; i1 = e; }
        float e1 = expf(v1 - v0);
        float inv = 1.f / (1.f + e1);
        g_top_idx[t * 2 + 0] = i0;  g_top_gate[t * 2 + 0] = inv;
        g_top_idx[t * 2 + 1] = i1;  g_top_gate[t * 2 + 1] = e1 * inv;
    }
}

__global__ void bin_kernel() {
    int i = blockIdx.x * blockDim.x + threadIdx.x;
    if (i >= T_TOK * 2) return;
    int e = g_top_idx[i];
    int p = atomicAdd(&g_counts[e], 1);
    g_slots[e * T_TOK + p] = i;
}

// ================= grouped GEMM core (mma.sync tf32) =================
// CTA: 256 threads = 8 warps (2 m x 4 n). Warp tile 64x32. CTA tile 128x128.
// SMEM stage: A[128][32]f + B[128][32]f, XOR swizzle at 16B granularity:
//   addr(row, col) = row*128 + ((col>>2 ^ (row&7))<<4) + (col&3)*4
#define STAGE_BYTES 32768
#define SMEM_CTRL   2048
#define SMEM_TOTAL_G (SMEM_CTRL + 2 * STAGE_BYTES)

// ---------------- gemm1: h = x @ w_in^T, fused SwiGLU -> g_act ----------------
// B rows interleaved: smem row 2j+h = w_in row (h*2048 + n0p + j); C col pairs
// (2p, 2p+1) = (h1_p, h2_p) land in one thread's (c0,c1)/(c2,c3).
__global__ void __launch_bounds__(256) gemm1_mma(const float* __restrict__ w1r) {
    extern __shared__ char sm[];
    int e = blockIdx.z;
    int cnt = g_counts[e];
    int m0 = blockIdx.y * 128;
    if (m0 >= cnt) return;
    int n0p = blockIdx.x * 64;                 // act-col base (pairs)
    int tid = threadIdx.x, lane = tid & 31, wid = tid >> 5;
    int g = lane >> 2, tg = lane & 3;
    int wm = wid & 1, wn = wid >> 1;

    int* rs = (int*)sm;                        // [128]
    const float** rowp = (const float**)(sm + 512);  // [128]
    if (tid < 128) {
        int m = m0 + tid;
        int slot = (m < cnt) ? g_slots[e * T_TOK + m] : -1;
        rs[tid] = slot;
        rowp[tid] = (slot >= 0) ? (g_xr + (size_t)(slot >> 1) * DM) : g_xr;
    }
    __syncthreads();

    uint32_t sb = smem_u32(sm);
    // fill mapping: 4 A-chunks + 4 B-chunks per thread
    int seg = tid & 7;
    const float* pA[4]; uint32_t dA[4];
    const float* pB[4]; uint32_t dB[4];
#pragma unroll
    for (int i = 0; i < 4; i++) {
        int row = i * 32 + (tid >> 3);
        pA[i] = rowp[row] + seg * 4;
        dA[i] = SMEM_CTRL + row * 128 + (((seg ^ (row & 7)) & 7) << 4);
        int j = row >> 1, h = row & 1;
        pB[i] = w1r + ((size_t)e * DFF2 + h * DFF + n0p + j) * DM + seg * 4;
        dB[i] = SMEM_CTRL + 16384 + row * 128 + (((seg ^ (row & 7)) & 7) << 4);
    }

#define FILL1(c_) do { \
        uint32_t so_ = ((c_) & 1) * STAGE_BYTES; \
        _Pragma("unroll") \
        for (int i = 0; i < 4; i++) { \
            cp16(sb + dA[i] + so_, pA[i]); pA[i] += KC; \
            cp16(sb + dB[i] + so_, pB[i]); pB[i] += KC; \
        } \
        CP_COMMIT(); \
    } while (0)

    float acc[4][4][4];
#pragma unroll
    for (int mt = 0; mt < 4; mt++)
#pragma unroll
        for (int nt = 0; nt < 4; nt++)
#pragma unroll
            for (int r = 0; r < 4; r++) acc[mt][nt][r] = 0.f;

    // per-thread fragment base offsets
    uint32_t aBase[4], bBase[4];
#pragma unroll
    for (int mt = 0; mt < 4; mt++) {
        int r0 = wm * 64 + mt * 16 + g;
        aBase[mt] = r0 * 128 + tg * 4;
    }
#pragma unroll
    for (int nt = 0; nt < 4; nt++) {
        int rn = wn * 32 + nt * 8 + g;
        bBase[nt] = 16384 + rn * 128 + tg * 4;
    }

    FILL1(0); FILL1(1);
    for (int c = 0; c < NCH1; c++) {
        if (c + 1 < NCH1) asm volatile("cp.async.wait_group 1;" ::: "memory");
        else              asm volatile("cp.async.wait_group 0;" ::: "memory");
        __syncthreads();
        char* st = sm + SMEM_CTRL + (c & 1) * STAGE_BYTES;
#pragma unroll
        for (int ks = 0; ks < 4; ks++) {
            uint32_t x0 = (((2 * ks) ^ g) & 7) << 4;
            uint32_t x1 = (((2 * ks + 1) ^ g) & 7) << 4;
            uint32_t a[4][4], b[4][2];
#pragma unroll
            for (int mt = 0; mt < 4; mt++) {
                a[mt][0] = *(const uint32_t*)(st + aBase[mt] + x0);
                a[mt][1] = *(const uint32_t*)(st + aBase[mt] + 1024 + x0);
                a[mt][2] = *(const uint32_t*)(st + aBase[mt] + x1);
                a[mt][3] = *(const uint32_t*)(st + aBase[mt] + 1024 + x1);
            }
#pragma unroll
            for (int nt = 0; nt < 4; nt++) {
                b[nt][0] = *(const uint32_t*)(st + bBase[nt] + x0);
                b[nt][1] = *(const uint32_t*)(st + bBase[nt] + x1);
            }
#pragma unroll
            for (int mt = 0; mt < 4; mt++)
#pragma unroll
                for (int nt = 0; nt < 4; nt++)
                    mma_tf32(acc[mt][nt], a[mt][0], a[mt][1], a[mt][2], a[mt][3],
                             b[nt][0], b[nt][1]);
        }
        __syncthreads();
        if (c + 2 < NCH1) FILL1(c + 2);
    }

    // epilogue: act = tf32(silu(h1)*h2), in registers
#pragma unroll
    for (int mt = 0; mt < 4; mt++) {
        int r0 = wm * 64 + mt * 16 + g;
        int s0 = rs[r0], s1 = rs[r0 + 8];
#pragma unroll
        for (int nt = 0; nt < 4; nt++) {
            int col = n0p + wn * 16 + nt * 4 + tg;
            if (s0 >= 0) {
                float h1 = acc[mt][nt][0], h2 = acc[mt][nt][1];
                float v = h1 / (1.f + expf(-h1)) * h2;
                g_act[(size_t)s0 * DFF + col] = __uint_as_float(tf32_rna(v));
            }
            if (s1 >= 0) {
                float h1 = acc[mt][nt][2], h2 = acc[mt][nt][3];
                float v = h1 / (1.f + expf(-h1)) * h2;
                g_act[(size_t)s1 * DFF + col] = __uint_as_float(tf32_rna(v));
            }
        }
    }
#undef FILL1
}

// ---------------- gemm2: y = act @ w_out^T -> g_y ----------------
__global__ void __launch_bounds__(256) gemm2_mma(const float* __restrict__ w2r) {
    extern __shared__ char sm[];
    int e = blockIdx.z;
    int cnt = g_counts[e];
    int m0 = blockIdx.y * 128;
    if (m0 >= cnt) return;
    int n0 = blockIdx.x * 128;
    int tid = threadIdx.x, lane = tid & 31, wid = tid >> 5;
    int g = lane >> 2, tg = lane & 3;
    int wm = wid & 1, wn = wid >> 1;

    int* rs = (int*)sm;
    const float** rowp = (const float**)(sm + 512);
    if (tid < 128) {
        int m = m0 + tid;
        int slot = (m < cnt) ? g_slots[e * T_TOK + m] : -1;
        rs[tid] = slot;
        rowp[tid] = (slot >= 0) ? (g_act + (size_t)slot * DFF) : g_act;
    }
    __syncthreads();

    uint32_t sb = smem_u32(sm);
    int seg = tid & 7;
    const float* pA[4]; uint32_t dA[4];
    const float* pB[4]; uint32_t dB[4];
#pragma unroll
    for (int i = 0; i < 4; i++) {
        int row = i * 32 + (tid >> 3);
        pA[i] = rowp[row] + seg * 4;
        dA[i] = SMEM_CTRL + row * 128 + (((seg ^ (row & 7)) & 7) << 4);
        pB[i] = w2r + ((size_t)e * DM + n0 + row) * DFF + seg * 4;
        dB[i] = SMEM_CTRL + 16384 + row * 128 + (((seg ^ (row & 7)) & 7) << 4);
    }

#define FILL2(c_) do { \
        uint32_t so_ = ((c_) & 1) * STAGE_BYTES; \
        _Pragma("unroll") \
        for (int i = 0; i < 4; i++) { \
            cp16(sb + dA[i] + so_, pA[i]); pA[i] += KC; \
            cp16(sb + dB[i] + so_, pB[i]); pB[i] += KC; \
        } \
        CP_COMMIT(); \
    } while (0)

    float acc[4][4][4];
#pragma unroll
    for (int mt = 0; mt < 4; mt++)
#pragma unroll
        for (int nt = 0; nt < 4; nt++)
#pragma unroll
            for (int r = 0; r < 4; r++) acc[mt][nt][r] = 0.f;

    uint32_t aBase[4], bBase[4];
#pragma unroll
    for (int mt = 0; mt < 4; mt++) {
        int r0 = wm * 64 + mt * 16 + g;
        aBase[mt] = r0 * 128 + tg * 4;
    }
#pragma unroll
    for (int nt = 0; nt < 4; nt++) {
        int rn = wn * 32 + nt * 8 + g;
        bBase[nt] = 16384 + rn * 128 + tg * 4;
    }

    FILL2(0); FILL2(1);
    for (int c = 0; c < NCH2; c++) {
        if (c + 1 < NCH2) asm volatile("cp.async.wait_group 1;" ::: "memory");
        else              asm volatile("cp.async.wait_group 0;" ::: "memory");
        __syncthreads();
        char* st = sm + SMEM_CTRL + (c & 1) * STAGE_BYTES;
#pragma unroll
        for (int ks = 0; ks < 4; ks++) {
            uint32_t x0 = (((2 * ks) ^ g) & 7) << 4;
            uint32_t x1 = (((2 * ks + 1) ^ g) & 7) << 4;
            uint32_t a[4][4], b[4][2];
#pragma unroll
            for (int mt = 0; mt < 4; mt++) {
                a[mt][0] = *(const uint32_t*)(st + aBase[mt] + x0);
                a[mt][1] = *(const uint32_t*)(st + aBase[mt] + 1024 + x0);
                a[mt][2] = *(const uint32_t*)(st + aBase[mt] + x1);
                a[mt][3] = *(const uint32_t*)(st + aBase[mt] + 1024 + x1);
            }
#pragma unroll
            for (int nt = 0; nt < 4; nt++) {
                b[nt][0] = *(const uint32_t*)(st + bBase[nt] + x0);
                b[nt][1] = *(const uint32_t*)(st + bBase[nt] + x1);
            }
#pragma unroll
            for (int mt = 0; mt < 4; mt++)
#pragma unroll
                for (int nt = 0; nt < 4; nt++)
                    mma_tf32(acc[mt][nt], a[mt][0], a[mt][1], a[mt][2], a[mt][3],
                             b[nt][0], b[nt][1]);
        }
        __syncthreads();
        if (c + 2 < NCH2) FILL2(c + 2);
    }

#pragma unroll
    for (int mt = 0; mt < 4; mt++) {
        int r0 = wm * 64 + mt * 16 + g;
        int s0 = rs[r0], s1 = rs[r0 + 8];
#pragma unroll
        for (int nt = 0; nt < 4; nt++) {
            int col = n0 + wn * 32 + nt * 8 + tg * 2;
            if (s0 >= 0) {
                float2 v = make_float2(acc[mt][nt][0], acc[mt][nt][1]);
                *(float2*)(g_y + (size_t)s0 * DM + col) = v;
            }
            if (s1 >= 0) {
                float2 v = make_float2(acc[mt][nt][2], acc[mt][nt][3]);
                *(float2*)(g_y + (size_t)s1 * DM + col) = v;
            }
        }
    }
#undef FILL2
}

// ---------------- combine: out[t] = g0*y[2t] + g1*y[2t+1] ----------------
__global__ void __launch_bounds__(256) combine_kernel(float* __restrict__ out) {
    int i = blockIdx.x * 256 + threadIdx.x;    // float4 index
    int t = i >> 8;
    int f = (i & 255) * 4;
    float g0 = g_top_gate[t * 2 + 0];
    float g1 = g_top_gate[t * 2 + 1];
    float4 a = *(const float4*)(g_y + (size_t)(t * 2 + 0) * DM + f);
    float4 b = *(const float4*)(g_y + (size_t)(t * 2 + 1) * DM + f);
    float4 o;
    o.x = g0 * a.x + g1 * b.x;
    o.y = g0 * a.y + g1 * b.y;
    o.z = g0 * a.z + g1 * b.z;
    o.w = g0 * a.w + g1 * b.w;
    *(float4*)(out + (size_t)t * DM + f) = o;
}

// ---------------- launcher ----------------
extern "C" void kernel_launch(void* const* d_in, const int* in_sizes, int n_in,
                              void* d_out, int out_size) {
    const float* x    = (const float*)d_in[0];   // [4096, 1024]
    const float* rw   = (const float*)d_in[1];   // [8, 1024]
    const float* w_in = (const float*)d_in[2];   // [8, 4096, 1024]
    const float* wout = (const float*)d_in[3];   // [8, 1024, 2048]
    float* out    = (float*)d_out;               // [4096, 1024]
    float* logits = out + (size_t)T_TOK * DM;    // [4096, 8]

    cudaFuncSetAttribute(gemm1_mma, cudaFuncAttributeMaxDynamicSharedMemorySize, SMEM_TOTAL_G);
    cudaFuncSetAttribute(gemm2_mma, cudaFuncAttributeMaxDynamicSharedMemorySize, SMEM_TOTAL_G);

    float* xr;  cudaGetSymbolAddress((void**)&xr,  g_xr);
    float* w1r; cudaGetSymbolAddress((void**)&w1r, g_w1r);
    float* w2r; cudaGetSymbolAddress((void**)&w2r, g_w2r);

    init_kernel<<<1, 32>>>();
    round_kernel<<<(T_TOK * DM / 4 + 255) / 256, 256>>>((const float4*)x, (float4*)xr, T_TOK * DM / 4);
    round_kernel<<<(NEXP * DFF2 * DM / 4 + 255) / 256, 256>>>((const float4*)w_in, (float4*)w1r, NEXP * DFF2 * DM / 4);
    round_kernel<<<(NEXP * DM * DFF / 4 + 255) / 256, 256>>>((const float4*)wout, (float4*)w2r, NEXP * DM * DFF / 4);
    router_kernel<<<T_TOK, 256>>>(x, rw, logits);
    bin_kernel<<<(T_TOK * 2 + 255) / 256, 256>>>();
    gemm1_mma<<<dim3(DFF / 64, T_TOK / 128, NEXP), 256, SMEM_TOTAL_G>>>(w1r);
    gemm2_mma<<<dim3(DM / 128, T_TOK / 128, NEXP), 256, SMEM_TOTAL_G>>>(w2r);
    combine_kernel<<<T_TOK * DM / 4 / 256, 256>>>(out);
}

// round 5
// speedup vs baseline: 4.0606x; 1.7114x over previous
#include <cuda_runtime.h>
#include <cuda_fp16.h>
#include <math.h>
#include <stdint.h>

#define T_TOK 4096
#define DM    1024
#define DFF   2048
#define DFF2  4096
#define NEXP  8
#define KC    64
#define NCH1  (DM/KC)     // 16
#define NCH2  (DFF/KC)    // 32

// ---------------- scratch ----------------
__device__ int    g_counts[NEXP];
__device__ int    g_slots[NEXP * T_TOK];
__device__ int    g_top_idx[T_TOK * 2];
__device__ float  g_top_gate[T_TOK * 2];
__device__ __half g_xr [(size_t)T_TOK * DM];          // fp16 x
__device__ __half g_w1r[(size_t)NEXP * DFF2 * DM];    // fp16 w_in
__device__ __half g_w2r[(size_t)NEXP * DM * DFF];     // fp16 w_out
__device__ __half g_act[(size_t)2 * T_TOK * DFF];     // fp16 swiglu output
__device__ float  g_y  [(size_t)2 * T_TOK * DM];      // per-slot gemm2 output (f32)

// ---------------- helpers ----------------
static __device__ __forceinline__ uint32_t smem_u32(const void* p) {
    uint32_t a;
    asm("{ .reg .u64 t; cvta.to.shared.u64 t, %1; cvt.u32.u64 %0, t; }" : "=r"(a) : "l"(p));
    return a;
}
static __device__ __forceinline__ void cp16(uint32_t d, const void* s) {
    asm volatile("cp.async.cg.shared.global [%0], [%1], 16;" :: "r"(d), "l"(s) : "memory");
}
#define CP_COMMIT() asm volatile("cp.async.commit_group;" ::: "memory")

static __device__ __forceinline__ void mma_f16(float* c,
        uint32_t a0, uint32_t a1, uint32_t a2, uint32_t a3,
        uint32_t b0, uint32_t b1) {
    asm volatile(
        "mma.sync.aligned.m16n8k16.row.col.f32.f16.f16.f32 "
        "{%0, %1, %2, %3}, {%4, %5, %6, %7}, {%8, %9}, {%0, %1, %2, %3};"
        : "+f"(c[0]), "+f"(c[1]), "+f"(c[2]), "+f"(c[3])
        : "r"(a0), "r"(a1), "r"(a2), "r"(a3), "r"(b0), "r"(b1));
}

// ---------------- small kernels ----------------
__global__ void init_kernel() {
    if (threadIdx.x < NEXP) g_counts[threadIdx.x] = 0;
}

// fp32 -> fp16 (rn), 4 elems per thread
__global__ void __launch_bounds__(256) round_kernel(const float4* __restrict__ s,
                                                    uint2* __restrict__ d, int n4) {
    int i = blockIdx.x * 256 + threadIdx.x;
    if (i >= n4) return;
    float4 v = s[i];
    __half2 h0 = __floats2half2_rn(v.x, v.y);
    __half2 h1 = __floats2half2_rn(v.z, v.w);
    uint2 o;
    o.x = *(uint32_t*)&h0;
    o.y = *(uint32_t*)&h1;
    d[i] = o;
}

__global__ void __launch_bounds__(256) router_kernel(
        const float* __restrict__ x, const float* __restrict__ rw,
        float* __restrict__ logits) {
    int t = blockIdx.x;
    int tid = threadIdx.x;
    const float* xr = x + (size_t)t * DM;
    float acc[NEXP];
#pragma unroll
    for (int e = 0; e < NEXP; e++) acc[e] = 0.f;
    for (int i = tid; i < DM; i += 256) {
        float xv = xr[i];
#pragma unroll
        for (int e = 0; e < NEXP; e++) acc[e] += xv * rw[e * DM + i];
    }
    __shared__ float red[NEXP][256];
    __shared__ float fin[NEXP];
#pragma unroll
    for (int e = 0; e < NEXP; e++) red[e][tid] = acc[e];
    __syncthreads();
    int w = tid >> 5, lane = tid & 31;
    if (w < NEXP) {
        float s = 0.f;
#pragma unroll
        for (int j = 0; j < 256; j += 32) s += red[w][lane + j];
#pragma unroll
        for (int o = 16; o > 0; o >>= 1) s += __shfl_down_sync(0xffffffffu, s, o);
        if (lane == 0) { fin[w] = s; logits[(size_t)t * NEXP + w] = s; }
    }
    __syncthreads();
    if (tid == 0) {
        int i0 = 0; float v0 = fin[0];
#pragma unroll
        for (int e = 1; e < NEXP; e++) if (fin[e] > v0) { v0 = fin[e]; i0 = e; }
        int i1 = -1; float v1 = -3.4e38f;
#pragma unroll
        for (int e = 0; e < NEXP; e++) if (e != i0 && fin[e] > v1) { v1 = fin[e]; i1 = e; }
        float e1 = expf(v1 - v0);
        float inv = 1.f / (1.f + e1);
        g_top_idx[t * 2 + 0] = i0;  g_top_gate[t * 2 + 0] = inv;
        g_top_idx[t * 2 + 1] = i1;  g_top_gate[t * 2 + 1] = e1 * inv;
    }
}

__global__ void bin_kernel() {
    int i = blockIdx.x * blockDim.x + threadIdx.x;
    if (i >= T_TOK * 2) return;
    int e = g_top_idx[i];
    int p = atomicAdd(&g_counts[e], 1);
    g_slots[e * T_TOK + p] = i;
}

// ================= grouped GEMM core (mma.sync fp16, m16n8k16) =================
// CTA: 256 threads = 8 warps (2 m x 4 n). Warp tile 64x32. CTA tile 128x128.
// SMEM stage: A[128 rows][64 halves=128B] + B[128][128B], XOR swizzle:
//   addr(row, kbyte) = row*128 + (((kbyte>>4) ^ (row&7))<<4) + (kbyte&15)
#define STAGE_BYTES 32768
#define SMEM_CTRL   2048
#define SMEM_TOTAL_G (SMEM_CTRL + 2 * STAGE_BYTES)

// ---------------- gemm1: h = x @ w_in^T, fused SwiGLU -> g_act ----------------
__global__ void __launch_bounds__(256) gemm1_mma(const __half* __restrict__ w1r) {
    extern __shared__ char sm[];
    int e = blockIdx.z;
    int cnt = g_counts[e];
    int m0 = blockIdx.y * 128;
    if (m0 >= cnt) return;
    int n0p = blockIdx.x * 64;                 // act-col base (pairs)
    int tid = threadIdx.x, lane = tid & 31, wid = tid >> 5;
    int g = lane >> 2, tg = lane & 3;
    int wm = wid & 1, wn = wid >> 1;

    int* rs = (int*)sm;                               // [128]
    const __half** rowp = (const __half**)(sm + 512); // [128]
    if (tid < 128) {
        int m = m0 + tid;
        int slot = (m < cnt) ? g_slots[e * T_TOK + m] : -1;
        rs[tid] = slot;
        rowp[tid] = (slot >= 0) ? (g_xr + (size_t)(slot >> 1) * DM) : g_xr;
    }
    __syncthreads();

    uint32_t sb = smem_u32(sm);
    int seg = tid & 7;                                // 16B segment within 128B row
    const __half* pA[4]; uint32_t dA[4];
    const __half* pB[4]; uint32_t dB[4];
#pragma unroll
    for (int i = 0; i < 4; i++) {
        int row = i * 32 + (tid >> 3);
        pA[i] = rowp[row] + seg * 8;
        dA[i] = SMEM_CTRL + row * 128 + (((seg ^ (row & 7)) & 7) << 4);
        int j = row >> 1, h = row & 1;
        pB[i] = w1r + ((size_t)e * DFF2 + h * DFF + n0p + j) * DM + seg * 8;
        dB[i] = SMEM_CTRL + 16384 + row * 128 + (((seg ^ (row & 7)) & 7) << 4);
    }

#define FILL1(c_) do { \
        uint32_t so_ = ((c_) & 1) * STAGE_BYTES; \
        _Pragma("unroll") \
        for (int i = 0; i < 4; i++) { \
            cp16(sb + dA[i] + so_, pA[i]); pA[i] += KC; \
            cp16(sb + dB[i] + so_, pB[i]); pB[i] += KC; \
        } \
        CP_COMMIT(); \
    } while (0)

    float acc[4][4][4];
#pragma unroll
    for (int mt = 0; mt < 4; mt++)
#pragma unroll
        for (int nt = 0; nt < 4; nt++)
#pragma unroll
            for (int r = 0; r < 4; r++) acc[mt][nt][r] = 0.f;

    uint32_t aBase[4], bBase[4];
#pragma unroll
    for (int mt = 0; mt < 4; mt++) {
        int r0 = wm * 64 + mt * 16 + g;
        aBase[mt] = r0 * 128 + tg * 4;
    }
#pragma unroll
    for (int nt = 0; nt < 4; nt++) {
        int rn = wn * 32 + nt * 8 + g;
        bBase[nt] = 16384 + rn * 128 + tg * 4;
    }

    FILL1(0); FILL1(1);
    for (int c = 0; c < NCH1; c++) {
        if (c + 1 < NCH1) asm volatile("cp.async.wait_group 1;" ::: "memory");
        else              asm volatile("cp.async.wait_group 0;" ::: "memory");
        __syncthreads();
        char* st = sm + SMEM_CTRL + (c & 1) * STAGE_BYTES;
#pragma unroll
        for (int ks = 0; ks < 4; ks++) {           // k16 per step, 4 steps = 64
            uint32_t x0 = (((2 * ks) ^ g) & 7) << 4;
            uint32_t x1 = (((2 * ks + 1) ^ g) & 7) << 4;
            uint32_t a[4][4], b[4][2];
#pragma unroll
            for (int mt = 0; mt < 4; mt++) {
                a[mt][0] = *(const uint32_t*)(st + aBase[mt] + x0);
                a[mt][1] = *(const uint32_t*)(st + aBase[mt] + 1024 + x0);
                a[mt][2] = *(const uint32_t*)(st + aBase[mt] + x1);
                a[mt][3] = *(const uint32_t*)(st + aBase[mt] + 1024 + x1);
            }
#pragma unroll
            for (int nt = 0; nt < 4; nt++) {
                b[nt][0] = *(const uint32_t*)(st + bBase[nt] + x0);
                b[nt][1] = *(const uint32_t*)(st + bBase[nt] + x1);
            }
#pragma unroll
            for (int mt = 0; mt < 4; mt++)
#pragma unroll
                for (int nt = 0; nt < 4; nt++)
                    mma_f16(acc[mt][nt], a[mt][0], a[mt][1], a[mt][2], a[mt][3],
                            b[nt][0], b[nt][1]);
        }
        __syncthreads();
        if (c + 2 < NCH1) FILL1(c + 2);
    }

    // epilogue: act = fp16(silu(h1)*h2), in registers
#pragma unroll
    for (int mt = 0; mt < 4; mt++) {
        int r0 = wm * 64 + mt * 16 + g;
        int s0 = rs[r0], s1 = rs[r0 + 8];
#pragma unroll
        for (int nt = 0; nt < 4; nt++) {
            int col = n0p + wn * 16 + nt * 4 + tg;
            if (s0 >= 0) {
                float h1 = acc[mt][nt][0], h2 = acc[mt][nt][1];
                float v = h1 / (1.f + expf(-h1)) * h2;
                g_act[(size_t)s0 * DFF + col] = __float2half_rn(v);
            }
            if (s1 >= 0) {
                float h1 = acc[mt][nt][2], h2 = acc[mt][nt][3];
                float v = h1 / (1.f + expf(-h1)) * h2;
                g_act[(size_t)s1 * DFF + col] = __float2half_rn(v);
            }
        }
    }
#undef FILL1
}

// ---------------- gemm2: y = act @ w_out^T -> g_y ----------------
__global__ void __launch_bounds__(256) gemm2_mma(const __half* __restrict__ w2r) {
    extern __shared__ char sm[];
    int e = blockIdx.z;
    int cnt = g_counts[e];
    int m0 = blockIdx.y * 128;
    if (m0 >= cnt) return;
    int n0 = blockIdx.x * 128;
    int tid = threadIdx.x, lane = tid & 31, wid = tid >> 5;
    int g = lane >> 2, tg = lane & 3;
    int wm = wid & 1, wn = wid >> 1;

    int* rs = (int*)sm;
    const __half** rowp = (const __half**)(sm + 512);
    if (tid < 128) {
        int m = m0 + tid;
        int slot = (m < cnt) ? g_slots[e * T_TOK + m] : -1;
        rs[tid] = slot;
        rowp[tid] = (slot >= 0) ? (g_act + (size_t)slot * DFF) : g_act;
    }
    __syncthreads();

    uint32_t sb = smem_u32(sm);
    int seg = tid & 7;
    const __half* pA[4]; uint32_t dA[4];
    const __half* pB[4]; uint32_t dB[4];
#pragma unroll
    for (int i = 0; i < 4; i++) {
        int row = i * 32 + (tid >> 3);
        pA[i] = rowp[row] + seg * 8;
        dA[i] = SMEM_CTRL + row * 128 + (((seg ^ (row & 7)) & 7) << 4);
        pB[i] = w2r + ((size_t)e * DM + n0 + row) * DFF + seg * 8;
        dB[i] = SMEM_CTRL + 16384 + row * 128 + (((seg ^ (row & 7)) & 7) << 4);
    }

#define FILL2(c_) do { \
        uint32_t so_ = ((c_) & 1) * STAGE_BYTES; \
        _Pragma("unroll") \
        for (int i = 0; i < 4; i++) { \
            cp16(sb + dA[i] + so_, pA[i]); pA[i] += KC; \
            cp16(sb + dB[i] + so_, pB[i]); pB[i] += KC; \
        } \
        CP_COMMIT(); \
    } while (0)

    float acc[4][4][4];
#pragma unroll
    for (int mt = 0; mt < 4; mt++)
#pragma unroll
        for (int nt = 0; nt < 4; nt++)
#pragma unroll
            for (int r = 0; r < 4; r++) acc[mt][nt][r] = 0.f;

    uint32_t aBase[4], bBase[4];
#pragma unroll
    for (int mt = 0; mt < 4; mt++) {
        int r0 = wm * 64 + mt * 16 + g;
        aBase[mt] = r0 * 128 + tg * 4;
    }
#pragma unroll
    for (int nt = 0; nt < 4; nt++) {
        int rn = wn * 32 + nt * 8 + g;
        bBase[nt] = 16384 + rn * 128 + tg * 4;
    }

    FILL2(0); FILL2(1);
    for (int c = 0; c < NCH2; c++) {
        if (c + 1 < NCH2) asm volatile("cp.async.wait_group 1;" ::: "memory");
        else              asm volatile("cp.async.wait_group 0;" ::: "memory");
        __syncthreads();
        char* st = sm + SMEM_CTRL + (c & 1) * STAGE_BYTES;
#pragma unroll
        for (int ks = 0; ks < 4; ks++) {
            uint32_t x0 = (((2 * ks) ^ g) & 7) << 4;
            uint32_t x1 = (((2 * ks + 1) ^ g) & 7) << 4;
            uint32_t a[4][4], b[4][2];
#pragma unroll
            for (int mt = 0; mt < 4; mt++) {
                a[mt][0] = *(const uint32_t*)(st + aBase[mt] + x0);
                a[mt][1] = *(const uint32_t*)(st + aBase[mt] + 1024 + x0);
                a[mt][2] = *(const uint32_t*)(st + aBase[mt] + x1);
                a[mt][3] = *(const uint32_t*)(st + aBase[mt] + 1024 + x1);
            }
#pragma unroll
            for (int nt = 0; nt < 4; nt++) {
                b[nt][0] = *(const uint32_t*)(st + bBase[nt] + x0);
                b[nt][1] = *(const uint32_t*)(st + bBase[nt] + x1);
            }
#pragma unroll
            for (int mt = 0; mt < 4; mt++)
#pragma unroll
                for (int nt = 0; nt < 4; nt++)
                    mma_f16(acc[mt][nt], a[mt][0], a[mt][1], a[mt][2], a[mt][3],
                            b[nt][0], b[nt][1]);
        }
        __syncthreads();
        if (c + 2 < NCH2) FILL2(c + 2);
    }

#pragma unroll
    for (int mt = 0; mt < 4; mt++) {
        int r0 = wm * 64 + mt * 16 + g;
        int s0 = rs[r0], s1 = rs[r0 + 8];
#pragma unroll
        for (int nt = 0; nt < 4; nt++) {
            int col = n0 + wn * 32 + nt * 8 + tg * 2;
            if (s0 >= 0) {
                float2 v = make_float2(acc[mt][nt][0], acc[mt][nt][1]);
                *(float2*)(g_y + (size_t)s0 * DM + col) = v;
            }
            if (s1 >= 0) {
                float2 v = make_float2(acc[mt][nt][2], acc[mt][nt][3]);
                *(float2*)(g_y + (size_t)s1 * DM + col) = v;
            }
        }
    }
#undef FILL2
}

// ---------------- combine: out[t] = g0*y[2t] + g1*y[2t+1] ----------------
__global__ void __launch_bounds__(256) combine_kernel(float* __restrict__ out) {
    int i = blockIdx.x * 256 + threadIdx.x;    // float4 index
    int t = i >> 8;
    int f = (i & 255) * 4;
    float g0 = g_top_gate[t * 2 + 0];
    float g1 = g_top_gate[t * 2 + 1];
    float4 a = *(const float4*)(g_y + (size_t)(t * 2 + 0) * DM + f);
    float4 b = *(const float4*)(g_y + (size_t)(t * 2 + 1) * DM + f);
    float4 o;
    o.x = g0 * a.x + g1 * b.x;
    o.y = g0 * a.y + g1 * b.y;
    o.z = g0 * a.z + g1 * b.z;
    o.w = g0 * a.w + g1 * b.w;
    *(float4*)(out + (size_t)t * DM + f) = o;
}

// ---------------- launcher ----------------
extern "C" void kernel_launch(void* const* d_in, const int* in_sizes, int n_in,
                              void* d_out, int out_size) {
    const float* x    = (const float*)d_in[0];   // [4096, 1024]
    const float* rw   = (const float*)d_in[1];   // [8, 1024]
    const float* w_in = (const float*)d_in[2];   // [8, 4096, 1024]
    const float* wout = (const float*)d_in[3];   // [8, 1024, 2048]
    float* out    = (float*)d_out;               // [4096, 1024]
    float* logits = out + (size_t)T_TOK * DM;    // [4096, 8]

    cudaFuncSetAttribute(gemm1_mma, cudaFuncAttributeMaxDynamicSharedMemorySize, SMEM_TOTAL_G);
    cudaFuncSetAttribute(gemm2_mma, cudaFuncAttributeMaxDynamicSharedMemorySize, SMEM_TOTAL_G);

    __half* xr;  cudaGetSymbolAddress((void**)&xr,  g_xr);
    __half* w1r; cudaGetSymbolAddress((void**)&w1r, g_w1r);
    __half* w2r; cudaGetSymbolAddress((void**)&w2r, g_w2r);

    init_kernel<<<1, 32>>>();
    round_kernel<<<(T_TOK * DM / 4 + 255) / 256, 256>>>((const float4*)x, (uint2*)xr, T_TOK * DM / 4);
    round_kernel<<<(NEXP * DFF2 * DM / 4 + 255) / 256, 256>>>((const float4*)w_in, (uint2*)w1r, NEXP * DFF2 * DM / 4);
    round_kernel<<<(NEXP * DM * DFF / 4 + 255) / 256, 256>>>((const float4*)wout, (uint2*)w2r, NEXP * DM * DFF / 4);
    router_kernel<<<T_TOK, 256>>>(x, rw, logits);
    bin_kernel<<<(T_TOK * 2 + 255) / 256, 256>>>();
    gemm1_mma<<<dim3(DFF / 64, T_TOK / 128, NEXP), 256, SMEM_TOTAL_G>>>(w1r);
    gemm2_mma<<<dim3(DM / 128, T_TOK / 128, NEXP), 256, SMEM_TOTAL_G>>>(w2r);
    combine_kernel<<<T_TOK * DM / 4 / 256, 256>>>(out);
}

// round 6
// speedup vs baseline: 6.9358x; 1.7081x over previous
#include <cuda_runtime.h>
#include <cuda_fp16.h>
#include <math.h>
#include <stdint.h>

#define T_TOK 4096
#define DM    1024
#define DFF   2048
#define DFF2  4096
#define NEXP  8
#define KC    64
#define NCH1  (DM/KC)     // 16
#define NCH2  (DFF/KC)    // 32

// ---------------- scratch ----------------
__device__ int    g_counts[NEXP];
__device__ int    g_slots[NEXP * T_TOK];
__device__ int    g_top_idx[T_TOK * 2];
__device__ float  g_top_gate[T_TOK * 2];
__device__ __half g_xr [(size_t)T_TOK * DM];          // fp16 x
__device__ __half g_w1r[(size_t)NEXP * DFF2 * DM];    // fp16 w_in
__device__ __half g_w2r[(size_t)NEXP * DM * DFF];     // fp16 w_out
__device__ __half g_act[(size_t)2 * T_TOK * DFF];     // fp16 swiglu output
__device__ float  g_y  [(size_t)2 * T_TOK * DM];      // per-slot gemm2 output (f32)

// ---------------- helpers ----------------
static __device__ __forceinline__ uint32_t smem_u32(const void* p) {
    uint32_t a;
    asm("{ .reg .u64 t; cvta.to.shared.u64 t, %1; cvt.u32.u64 %0, t; }" : "=r"(a) : "l"(p));
    return a;
}
static __device__ __forceinline__ void cp16(uint32_t d, const void* s) {
    asm volatile("cp.async.cg.shared.global [%0], [%1], 16;" :: "r"(d), "l"(s) : "memory");
}
#define CP_COMMIT() asm volatile("cp.async.commit_group;" ::: "memory")

static __device__ __forceinline__ void mma_f16(float* c,
        uint32_t a0, uint32_t a1, uint32_t a2, uint32_t a3,
        uint32_t b0, uint32_t b1) {
    asm volatile(
        "mma.sync.aligned.m16n8k16.row.col.f32.f16.f16.f32 "
        "{%0, %1, %2, %3}, {%4, %5, %6, %7}, {%8, %9}, {%0, %1, %2, %3};"
        : "+f"(c[0]), "+f"(c[1]), "+f"(c[2]), "+f"(c[3])
        : "r"(a0), "r"(a1), "r"(a2), "r"(a3), "r"(b0), "r"(b1));
}
static __device__ __forceinline__ void ldsm4(uint32_t* r, uint32_t addr) {
    asm volatile("ldmatrix.sync.aligned.m8n8.x4.shared.b16 {%0,%1,%2,%3}, [%4];"
        : "=r"(r[0]), "=r"(r[1]), "=r"(r[2]), "=r"(r[3]) : "r"(addr));
}

// ---------------- small kernels ----------------
__global__ void init_kernel() {
    if (threadIdx.x < NEXP) g_counts[threadIdx.x] = 0;
}

// fp32 -> fp16 (rn), 16 elems (4 x float4) per thread for MLP
__global__ void __launch_bounds__(256) round_kernel(const float4* __restrict__ s,
                                                    uint2* __restrict__ d, int n4) {
    int i0 = (blockIdx.x * 256 + threadIdx.x) * 4;
    if (i0 + 3 >= n4) {
        for (int j = 0; j < 4 && i0 + j < n4; j++) {
            float4 v = s[i0 + j];
            __half2 h0 = __floats2half2_rn(v.x, v.y);
            __half2 h1 = __floats2half2_rn(v.z, v.w);
            uint2 o; o.x = *(uint32_t*)&h0; o.y = *(uint32_t*)&h1;
            d[i0 + j] = o;
        }
        return;
    }
    float4 v[4];
#pragma unroll
    for (int j = 0; j < 4; j++) v[j] = s[i0 + j];
#pragma unroll
    for (int j = 0; j < 4; j++) {
        __half2 h0 = __floats2half2_rn(v[j].x, v[j].y);
        __half2 h1 = __floats2half2_rn(v[j].z, v[j].w);
        uint2 o; o.x = *(uint32_t*)&h0; o.y = *(uint32_t*)&h1;
        d[i0 + j] = o;
    }
}

__global__ void __launch_bounds__(256) router_kernel(
        const float* __restrict__ x, const float* __restrict__ rw,
        float* __restrict__ logits) {
    int t = blockIdx.x;
    int tid = threadIdx.x;
    const float* xr = x + (size_t)t * DM;
    float acc[NEXP];
#pragma unroll
    for (int e = 0; e < NEXP; e++) acc[e] = 0.f;
    for (int i = tid; i < DM; i += 256) {
        float xv = xr[i];
#pragma unroll
        for (int e = 0; e < NEXP; e++) acc[e] += xv * rw[e * DM + i];
    }
    __shared__ float red[NEXP][256];
    __shared__ float fin[NEXP];
#pragma unroll
    for (int e = 0; e < NEXP; e++) red[e][tid] = acc[e];
    __syncthreads();
    int w = tid >> 5, lane = tid & 31;
    if (w < NEXP) {
        float s = 0.f;
#pragma unroll
        for (int j = 0; j < 256; j += 32) s += red[w][lane + j];
#pragma unroll
        for (int o = 16; o > 0; o >>= 1) s += __shfl_down_sync(0xffffffffu, s, o);
        if (lane == 0) { fin[w] = s; logits[(size_t)t * NEXP + w] = s; }
    }
    __syncthreads();
    if (tid == 0) {
        int i0 = 0; float v0 = fin[0];
#pragma unroll
        for (int e = 1; e < NEXP; e++) if (fin[e] > v0) { v0 = fin[e]; i0 = e; }
        int i1 = -1; float v1 = -3.4e38f;
#pragma unroll
        for (int e = 0; e < NEXP; e++) if (e != i0 && fin[e] > v1) { v1 = fin[e]; i1 = e; }
        float e1 = expf(v1 - v0);
        float inv = 1.f / (1.f + e1);
        g_top_idx[t * 2 + 0] = i0;  g_top_gate[t * 2 + 0] = inv;
        g_top_idx[t * 2 + 1] = i1;  g_top_gate[t * 2 + 1] = e1 * inv;
    }
}

__global__ void bin_kernel() {
    int i = blockIdx.x * blockDim.x + threadIdx.x;
    if (i >= T_TOK * 2) return;
    int e = g_top_idx[i];
    int p = atomicAdd(&g_counts[e], 1);
    g_slots[e * T_TOK + p] = i;
}

// ================= grouped GEMM core (mma.sync fp16 + ldmatrix) =================
// CTA: 256 threads = 8 warps (2 m x 4 n). Warp tile 64x32. CTA tile 128x128.
// SMEM stage: A[128 rows][128B] + B[128][128B], XOR swizzle:
//   addr(row, seg16B) = row*128 + ((seg ^ (row&7))<<4)
#define STAGE_BYTES 32768
#define SMEM_CTRL   2048
#define SMEM_TOTAL_G (SMEM_CTRL + 2 * STAGE_BYTES)

// ---------------- gemm1: h = x @ w_in^T, fused SwiGLU -> g_act ----------------
__global__ void __launch_bounds__(256, 2) gemm1_mma(const __half* __restrict__ w1r) {
    extern __shared__ char sm[];
    int e = blockIdx.z;
    int cnt = g_counts[e];
    int m0 = blockIdx.y * 128;
    if (m0 >= cnt) return;
    int n0p = blockIdx.x * 64;                 // act-col base (pairs)
    int tid = threadIdx.x, lane = tid & 31, wid = tid >> 5;
    int g = lane >> 2, tg = lane & 3;
    int wm = wid & 1, wn = wid >> 1;

    int* rs = (int*)sm;                               // [128]
    const __half** rowp = (const __half**)(sm + 512); // [128]
    if (tid < 128) {
        int m = m0 + tid;
        int slot = (m < cnt) ? g_slots[e * T_TOK + m] : -1;
        rs[tid] = slot;
        rowp[tid] = (slot >= 0) ? (g_xr + (size_t)(slot >> 1) * DM) : g_xr;
    }
    __syncthreads();

    uint32_t sb = smem_u32(sm);
    int seg = tid & 7;                                // 16B segment within 128B row
    const __half* pA[4]; uint32_t dA[4];
    const __half* pB[4]; uint32_t dB[4];
#pragma unroll
    for (int i = 0; i < 4; i++) {
        int row = i * 32 + (tid >> 3);
        pA[i] = rowp[row] + seg * 8;
        dA[i] = SMEM_CTRL + row * 128 + (((seg ^ (row & 7)) & 7) << 4);
        int j = row >> 1, h = row & 1;
        pB[i] = w1r + ((size_t)e * DFF2 + h * DFF + n0p + j) * DM + seg * 8;
        dB[i] = SMEM_CTRL + 16384 + row * 128 + (((seg ^ (row & 7)) & 7) << 4);
    }

#define FILL1(c_) do { \
        uint32_t so_ = ((c_) & 1) * STAGE_BYTES; \
        _Pragma("unroll") \
        for (int i = 0; i < 4; i++) { \
            cp16(sb + dA[i] + so_, pA[i]); pA[i] += KC; \
            cp16(sb + dB[i] + so_, pB[i]); pB[i] += KC; \
        } \
        CP_COMMIT(); \
    } while (0)

    float acc[4][4][4];
#pragma unroll
    for (int mt = 0; mt < 4; mt++)
#pragma unroll
        for (int nt = 0; nt < 4; nt++)
#pragma unroll
            for (int r = 0; r < 4; r++) acc[mt][nt][r] = 0.f;

    // ldmatrix per-lane terms
    int g8 = lane >> 3, lr = lane & 7;
    uint32_t rx = (uint32_t)lr << 4;
    int aHalf = g8 >> 1;               // k-half for A matrices
    int aRow8 = (g8 & 1) * 8;          // +8 rows for m-hi matrices
    int bHalf = g8 & 1;                // k-half for B matrices
    int bRow8 = (g8 >> 1) * 8;         // +8 rows for n-hi matrices
    uint32_t aTerm[4], bTerm[2];
#pragma unroll
    for (int mt = 0; mt < 4; mt++) {
        int row = wm * 64 + mt * 16 + aRow8 + lr;
        aTerm[mt] = sb + SMEM_CTRL + row * 128;
    }
#pragma unroll
    for (int ntp = 0; ntp < 2; ntp++) {
        int row = wn * 32 + ntp * 16 + bRow8 + lr;
        bTerm[ntp] = sb + SMEM_CTRL + 16384 + row * 128;
    }

    FILL1(0); FILL1(1);
    for (int c = 0; c < NCH1; c++) {
        if (c + 1 < NCH1) asm volatile("cp.async.wait_group 1;" ::: "memory");
        else              asm volatile("cp.async.wait_group 0;" ::: "memory");
        __syncthreads();
        uint32_t so = (c & 1) * STAGE_BYTES;
#pragma unroll
        for (int ks = 0; ks < 4; ks++) {           // k16 per step, 4 steps = 64
            uint32_t aoff = so + ((((uint32_t)(ks * 2 + aHalf)) << 4) ^ rx);
            uint32_t boff = so + ((((uint32_t)(ks * 2 + bHalf)) << 4) ^ rx);
            uint32_t a[4][4], b[4][2];
#pragma unroll
            for (int mt = 0; mt < 4; mt++) ldsm4(a[mt], aTerm[mt] + aoff);
#pragma unroll
            for (int ntp = 0; ntp < 2; ntp++) {
                uint32_t bb[4];
                ldsm4(bb, bTerm[ntp] + boff);
                b[2 * ntp][0] = bb[0]; b[2 * ntp][1] = bb[1];
                b[2 * ntp + 1][0] = bb[2]; b[2 * ntp + 1][1] = bb[3];
            }
#pragma unroll
            for (int mt = 0; mt < 4; mt++)
#pragma unroll
                for (int nt = 0; nt < 4; nt++)
                    mma_f16(acc[mt][nt], a[mt][0], a[mt][1], a[mt][2], a[mt][3],
                            b[nt][0], b[nt][1]);
        }
        __syncthreads();
        if (c + 2 < NCH1) FILL1(c + 2);
    }

    // epilogue: act = fp16(silu(h1)*h2), in registers
#pragma unroll
    for (int mt = 0; mt < 4; mt++) {
        int r0 = wm * 64 + mt * 16 + g;
        int s0 = rs[r0], s1 = rs[r0 + 8];
#pragma unroll
        for (int nt = 0; nt < 4; nt++) {
            int col = n0p + wn * 16 + nt * 4 + tg;
            if (s0 >= 0) {
                float h1 = acc[mt][nt][0], h2 = acc[mt][nt][1];
                float v = h1 / (1.f + expf(-h1)) * h2;
                g_act[(size_t)s0 * DFF + col] = __float2half_rn(v);
            }
            if (s1 >= 0) {
                float h1 = acc[mt][nt][2], h2 = acc[mt][nt][3];
                float v = h1 / (1.f + expf(-h1)) * h2;
                g_act[(size_t)s1 * DFF + col] = __float2half_rn(v);
            }
        }
    }
#undef FILL1
}

// ---------------- gemm2: y = act @ w_out^T -> g_y ----------------
__global__ void __launch_bounds__(256, 2) gemm2_mma(const __half* __restrict__ w2r) {
    extern __shared__ char sm[];
    int e = blockIdx.z;
    int cnt = g_counts[e];
    int m0 = blockIdx.y * 128;
    if (m0 >= cnt) return;
    int n0 = blockIdx.x * 128;
    int tid = threadIdx.x, lane = tid & 31, wid = tid >> 5;
    int g = lane >> 2, tg = lane & 3;
    int wm = wid & 1, wn = wid >> 1;

    int* rs = (int*)sm;
    const __half** rowp = (const __half**)(sm + 512);
    if (tid < 128) {
        int m = m0 + tid;
        int slot = (m < cnt) ? g_slots[e * T_TOK + m] : -1;
        rs[tid] = slot;
        rowp[tid] = (slot >= 0) ? (g_act + (size_t)slot * DFF) : g_act;
    }
    __syncthreads();

    uint32_t sb = smem_u32(sm);
    int seg = tid & 7;
    const __half* pA[4]; uint32_t dA[4];
    const __half* pB[4]; uint32_t dB[4];
#pragma unroll
    for (int i = 0; i < 4; i++) {
        int row = i * 32 + (tid >> 3);
        pA[i] = rowp[row] + seg * 8;
        dA[i] = SMEM_CTRL + row * 128 + (((seg ^ (row & 7)) & 7) << 4);
        pB[i] = w2r + ((size_t)e * DM + n0 + row) * DFF + seg * 8;
        dB[i] = SMEM_CTRL + 16384 + row * 128 + (((seg ^ (row & 7)) & 7) << 4);
    }

#define FILL2(c_) do { \
        uint32_t so_ = ((c_) & 1) * STAGE_BYTES; \
        _Pragma("unroll") \
        for (int i = 0; i < 4; i++) { \
            cp16(sb + dA[i] + so_, pA[i]); pA[i] += KC; \
            cp16(sb + dB[i] + so_, pB[i]); pB[i] += KC; \
        } \
        CP_COMMIT(); \
    } while (0)

    float acc[4][4][4];
#pragma unroll
    for (int mt = 0; mt < 4; mt++)
#pragma unroll
        for (int nt = 0; nt < 4; nt++)
#pragma unroll
            for (int r = 0; r < 4; r++) acc[mt][nt][r] = 0.f;

    int g8 = lane >> 3, lr = lane & 7;
    uint32_t rx = (uint32_t)lr << 4;
    int aHalf = g8 >> 1;
    int aRow8 = (g8 & 1) * 8;
    int bHalf = g8 & 1;
    int bRow8 = (g8 >> 1) * 8;
    uint32_t aTerm[4], bTerm[2];
#pragma unroll
    for (int mt = 0; mt < 4; mt++) {
        int row = wm * 64 + mt * 16 + aRow8 + lr;
        aTerm[mt] = sb + SMEM_CTRL + row * 128;
    }
#pragma unroll
    for (int ntp = 0; ntp < 2; ntp++) {
        int row = wn * 32 + ntp * 16 + bRow8 + lr;
        bTerm[ntp] = sb + SMEM_CTRL + 16384 + row * 128;
    }

    FILL2(0); FILL2(1);
    for (int c = 0; c < NCH2; c++) {
        if (c + 1 < NCH2) asm volatile("cp.async.wait_group 1;" ::: "memory");
        else              asm volatile("cp.async.wait_group 0;" ::: "memory");
        __syncthreads();
        uint32_t so = (c & 1) * STAGE_BYTES;
#pragma unroll
        for (int ks = 0; ks < 4; ks++) {
            uint32_t aoff = so + ((((uint32_t)(ks * 2 + aHalf)) << 4) ^ rx);
            uint32_t boff = so + ((((uint32_t)(ks * 2 + bHalf)) << 4) ^ rx);
            uint32_t a[4][4], b[4][2];
#pragma unroll
            for (int mt = 0; mt < 4; mt++) ldsm4(a[mt], aTerm[mt] + aoff);
#pragma unroll
            for (int ntp = 0; ntp < 2; ntp++) {
                uint32_t bb[4];
                ldsm4(bb, bTerm[ntp] + boff);
                b[2 * ntp][0] = bb[0]; b[2 * ntp][1] = bb[1];
                b[2 * ntp + 1][0] = bb[2]; b[2 * ntp + 1][1] = bb[3];
            }
#pragma unroll
            for (int mt = 0; mt < 4; mt++)
#pragma unroll
                for (int nt = 0; nt < 4; nt++)
                    mma_f16(acc[mt][nt], a[mt][0], a[mt][1], a[mt][2], a[mt][3],
                            b[nt][0], b[nt][1]);
        }
        __syncthreads();
        if (c + 2 < NCH2) FILL2(c + 2);
    }

#pragma unroll
    for (int mt = 0; mt < 4; mt++) {
        int r0 = wm * 64 + mt * 16 + g;
        int s0 = rs[r0], s1 = rs[r0 + 8];
#pragma unroll
        for (int nt = 0; nt < 4; nt++) {
            int col = n0 + wn * 32 + nt * 8 + tg * 2;
            if (s0 >= 0) {
                float2 v = make_float2(acc[mt][nt][0], acc[mt][nt][1]);
                *(float2*)(g_y + (size_t)s0 * DM + col) = v;
            }
            if (s1 >= 0) {
                float2 v = make_float2(acc[mt][nt][2], acc[mt][nt][3]);
                *(float2*)(g_y + (size_t)s1 * DM + col) = v;
            }
        }
    }
#undef FILL2
}

// ---------------- combine: out[t] = g0*y[2t] + g1*y[2t+1] ----------------
__global__ void __launch_bounds__(256) combine_kernel(float* __restrict__ out) {
    int i = blockIdx.x * 256 + threadIdx.x;    // float4 index
    int t = i >> 8;
    int f = (i & 255) * 4;
    float g0 = g_top_gate[t * 2 + 0];
    float g1 = g_top_gate[t * 2 + 1];
    float4 a = *(const float4*)(g_y + (size_t)(t * 2 + 0) * DM + f);
    float4 b = *(const float4*)(g_y + (size_t)(t * 2 + 1) * DM + f);
    float4 o;
    o.x = g0 * a.x + g1 * b.x;
    o.y = g0 * a.y + g1 * b.y;
    o.z = g0 * a.z + g1 * b.z;
    o.w = g0 * a.w + g1 * b.w;
    *(float4*)(out + (size_t)t * DM + f) = o;
}

// ---------------- launcher ----------------
extern "C" void kernel_launch(void* const* d_in, const int* in_sizes, int n_in,
                              void* d_out, int out_size) {
    const float* x    = (const float*)d_in[0];   // [4096, 1024]
    const float* rw   = (const float*)d_in[1];   // [8, 1024]
    const float* w_in = (const float*)d_in[2];   // [8, 4096, 1024]
    const float* wout = (const float*)d_in[3];   // [8, 1024, 2048]
    float* out    = (float*)d_out;               // [4096, 1024]
    float* logits = out + (size_t)T_TOK * DM;    // [4096, 8]

    cudaFuncSetAttribute(gemm1_mma, cudaFuncAttributeMaxDynamicSharedMemorySize, SMEM_TOTAL_G);
    cudaFuncSetAttribute(gemm2_mma, cudaFuncAttributeMaxDynamicSharedMemorySize, SMEM_TOTAL_G);

    __half* xr;  cudaGetSymbolAddress((void**)&xr,  g_xr);
    __half* w1r; cudaGetSymbolAddress((void**)&w1r, g_w1r);
    __half* w2r; cudaGetSymbolAddress((void**)&w2r, g_w2r);

    init_kernel<<<1, 32>>>();
    {
        int n4 = T_TOK * DM / 4;
        round_kernel<<<(n4 / 4 + 255) / 256, 256>>>((const float4*)x, (uint2*)xr, n4);
    }
    {
        int n4 = NEXP * DFF2 * DM / 4;
        round_kernel<<<(n4 / 4 + 255) / 256, 256>>>((const float4*)w_in, (uint2*)w1r, n4);
    }
    {
        int n4 = NEXP * DM * DFF / 4;
        round_kernel<<<(n4 / 4 + 255) / 256, 256>>>((const float4*)wout, (uint2*)w2r, n4);
    }
    router_kernel<<<T_TOK, 256>>>(x, rw, logits);
    bin_kernel<<<(T_TOK * 2 + 255) / 256, 256>>>();
    gemm1_mma<<<dim3(DFF / 64, T_TOK / 128, NEXP), 256, SMEM_TOTAL_G>>>(w1r);
    gemm2_mma<<<dim3(DM / 128, T_TOK / 128, NEXP), 256, SMEM_TOTAL_G>>>(w2r);
    combine_kernel<<<T_TOK * DM / 4 / 256, 256>>>(out);
}

// round 7
// speedup vs baseline: 6.9567x; 1.0030x over previous
#include <cuda_runtime.h>
#include <cuda_fp16.h>
#include <math.h>
#include <stdint.h>

#define T_TOK 4096
#define DM    1024
#define DFF   2048
#define DFF2  4096
#define NEXP  8
#define KC    64
#define NCH1  (DM/KC)     // 16
#define NCH2  (DFF/KC)    // 32

// ---------------- scratch ----------------
__device__ int    g_counts[NEXP];
__device__ int    g_slots[NEXP * T_TOK];
__device__ int    g_top_idx[T_TOK * 2];
__device__ float  g_top_gate[T_TOK * 2];
__device__ __half g_xr [(size_t)T_TOK * DM];          // fp16 x
__device__ __half g_w1r[(size_t)NEXP * DFF2 * DM];    // fp16 w_in
__device__ __half g_w2r[(size_t)NEXP * DM * DFF];     // fp16 w_out
__device__ __half g_act[(size_t)2 * T_TOK * DFF];     // fp16 swiglu output
__device__ float  g_y  [(size_t)2 * T_TOK * DM];      // per-slot gemm2 output (f32)

// ---------------- helpers ----------------
static __device__ __forceinline__ uint32_t smem_u32(const void* p) {
    uint32_t a;
    asm("{ .reg .u64 t; cvta.to.shared.u64 t, %1; cvt.u32.u64 %0, t; }" : "=r"(a) : "l"(p));
    return a;
}
static __device__ __forceinline__ void cp16(uint32_t d, const void* s) {
    asm volatile("cp.async.cg.shared.global [%0], [%1], 16;" :: "r"(d), "l"(s) : "memory");
}
#define CP_COMMIT() asm volatile("cp.async.commit_group;" ::: "memory")

static __device__ __forceinline__ void mma_f16(float* c,
        uint32_t a0, uint32_t a1, uint32_t a2, uint32_t a3,
        uint32_t b0, uint32_t b1) {
    asm volatile(
        "mma.sync.aligned.m16n8k16.row.col.f32.f16.f16.f32 "
        "{%0, %1, %2, %3}, {%4, %5, %6, %7}, {%8, %9}, {%0, %1, %2, %3};"
        : "+f"(c[0]), "+f"(c[1]), "+f"(c[2]), "+f"(c[3])
        : "r"(a0), "r"(a1), "r"(a2), "r"(a3), "r"(b0), "r"(b1));
}
static __device__ __forceinline__ void ldsm4(uint32_t* r, uint32_t addr) {
    asm volatile("ldmatrix.sync.aligned.m8n8.x4.shared.b16 {%0,%1,%2,%3}, [%4];"
        : "=r"(r[0]), "=r"(r[1]), "=r"(r[2]), "=r"(r[3]) : "r"(addr));
}

// ---------------- small kernels ----------------
__global__ void init_kernel() {
    if (threadIdx.x < NEXP) g_counts[threadIdx.x] = 0;
}

// fused fp32 -> fp16 (rn) over x, w_in, w_out: 16 elems per thread
__global__ void __launch_bounds__(256) round_all_kernel(
        const float4* __restrict__ x,  uint2* __restrict__ xr,  int nx,
        const float4* __restrict__ w1, uint2* __restrict__ w1r, int n1,
        const float4* __restrict__ w2, uint2* __restrict__ w2r, int n2) {
    int i0 = (blockIdx.x * 256 + threadIdx.x) * 4;
    const float4* s; uint2* d; int n;
    if (i0 < nx)            { s = x;  d = xr;  n = nx; }
    else if ((i0 -= nx) < n1) { s = w1; d = w1r; n = n1; }
    else if ((i0 -= n1) < n2) { s = w2; d = w2r; n = n2; }
    else return;
    if (i0 + 3 < n) {
        float4 v[4];
#pragma unroll
        for (int j = 0; j < 4; j++) v[j] = s[i0 + j];
#pragma unroll
        for (int j = 0; j < 4; j++) {
            __half2 h0 = __floats2half2_rn(v[j].x, v[j].y);
            __half2 h1 = __floats2half2_rn(v[j].z, v[j].w);
            uint2 o; o.x = *(uint32_t*)&h0; o.y = *(uint32_t*)&h1;
            d[i0 + j] = o;
        }
    } else {
        for (int j = 0; j < 4 && i0 + j < n; j++) {
            float4 v = s[i0 + j];
            __half2 h0 = __floats2half2_rn(v.x, v.y);
            __half2 h1 = __floats2half2_rn(v.z, v.w);
            uint2 o; o.x = *(uint32_t*)&h0; o.y = *(uint32_t*)&h1;
            d[i0 + j] = o;
        }
    }
}

__global__ void __launch_bounds__(256) router_kernel(
        const float* __restrict__ x, const float* __restrict__ rw,
        float* __restrict__ logits) {
    int t = blockIdx.x;
    int tid = threadIdx.x;
    const float* xr = x + (size_t)t * DM;
    float acc[NEXP];
#pragma unroll
    for (int e = 0; e < NEXP; e++) acc[e] = 0.f;
    for (int i = tid; i < DM; i += 256) {
        float xv = xr[i];
#pragma unroll
        for (int e = 0; e < NEXP; e++) acc[e] += xv * rw[e * DM + i];
    }
    __shared__ float red[NEXP][256];
    __shared__ float fin[NEXP];
#pragma unroll
    for (int e = 0; e < NEXP; e++) red[e][tid] = acc[e];
    __syncthreads();
    int w = tid >> 5, lane = tid & 31;
    if (w < NEXP) {
        float s = 0.f;
#pragma unroll
        for (int j = 0; j < 256; j += 32) s += red[w][lane + j];
#pragma unroll
        for (int o = 16; o > 0; o >>= 1) s += __shfl_down_sync(0xffffffffu, s, o);
        if (lane == 0) { fin[w] = s; logits[(size_t)t * NEXP + w] = s; }
    }
    __syncthreads();
    if (tid == 0) {
        int i0 = 0; float v0 = fin[0];
#pragma unroll
        for (int e = 1; e < NEXP; e++) if (fin[e] > v0) { v0 = fin[e]; i0 = e; }
        int i1 = -1; float v1 = -3.4e38f;
#pragma unroll
        for (int e = 0; e < NEXP; e++) if (e != i0 && fin[e] > v1) { v1 = fin[e]; i1 = e; }
        float e1 = expf(v1 - v0);
        float inv = 1.f / (1.f + e1);
        g_top_idx[t * 2 + 0] = i0;  g_top_gate[t * 2 + 0] = inv;
        g_top_idx[t * 2 + 1] = i1;  g_top_gate[t * 2 + 1] = e1 * inv;
    }
}

__global__ void bin_kernel() {
    int i = blockIdx.x * blockDim.x + threadIdx.x;
    if (i >= T_TOK * 2) return;
    int e = g_top_idx[i];
    int p = atomicAdd(&g_counts[e], 1);
    g_slots[e * T_TOK + p] = i;
}

// ================= grouped GEMM core (mma.sync fp16 + ldmatrix, 3-stage) =========
// CTA: 256 threads = 8 warps (2 m x 4 n). Warp tile 64x32. CTA tile 128x128.
// SMEM stage: A[128 rows][128B] + B[128][128B], XOR swizzle:
//   addr(row, seg16B) = row*128 + ((seg ^ (row&7))<<4)
#define STAGE_BYTES 32768
#define NSTAGE      3
#define SMEM_CTRL   2048
#define SMEM_TOTAL_G (SMEM_CTRL + NSTAGE * STAGE_BYTES)

// ---------------- gemm1: h = x @ w_in^T, fused SwiGLU -> g_act ----------------
__global__ void __launch_bounds__(256, 2) gemm1_mma(const __half* __restrict__ w1r) {
    extern __shared__ char sm[];
    int e = blockIdx.z;
    int cnt = g_counts[e];
    int m0 = blockIdx.y * 128;
    if (m0 >= cnt) return;
    int n0p = blockIdx.x * 64;                 // act-col base (pairs)
    int tid = threadIdx.x, lane = tid & 31, wid = tid >> 5;
    int g = lane >> 2, tg = lane & 3;
    int wm = wid & 1, wn = wid >> 1;

    int* rs = (int*)sm;                               // [128]
    const __half** rowp = (const __half**)(sm + 512); // [128]
    if (tid < 128) {
        int m = m0 + tid;
        int slot = (m < cnt) ? g_slots[e * T_TOK + m] : -1;
        rs[tid] = slot;
        rowp[tid] = (slot >= 0) ? (g_xr + (size_t)(slot >> 1) * DM) : g_xr;
    }
    __syncthreads();

    uint32_t sb = smem_u32(sm);
    int seg = tid & 7;                                // 16B segment within 128B row
    const __half* pA[4]; uint32_t dA[4];
    const __half* pB[4]; uint32_t dB[4];
#pragma unroll
    for (int i = 0; i < 4; i++) {
        int row = i * 32 + (tid >> 3);
        pA[i] = rowp[row] + seg * 8;
        dA[i] = SMEM_CTRL + row * 128 + (((seg ^ (row & 7)) & 7) << 4);
        int j = row >> 1, h = row & 1;
        pB[i] = w1r + ((size_t)e * DFF2 + h * DFF + n0p + j) * DM + seg * 8;
        dB[i] = SMEM_CTRL + 16384 + row * 128 + (((seg ^ (row & 7)) & 7) << 4);
    }

#define FILL1(c_) do { \
        uint32_t so_ = (uint32_t)((c_) % NSTAGE) * STAGE_BYTES; \
        _Pragma("unroll") \
        for (int i = 0; i < 4; i++) { \
            cp16(sb + dA[i] + so_, pA[i]); pA[i] += KC; \
            cp16(sb + dB[i] + so_, pB[i]); pB[i] += KC; \
        } \
        CP_COMMIT(); \
    } while (0)

    float acc[4][4][4];
#pragma unroll
    for (int mt = 0; mt < 4; mt++)
#pragma unroll
        for (int nt = 0; nt < 4; nt++)
#pragma unroll
            for (int r = 0; r < 4; r++) acc[mt][nt][r] = 0.f;

    // ldmatrix per-lane terms
    int g8 = lane >> 3, lr = lane & 7;
    uint32_t rx = (uint32_t)lr << 4;
    int aHalf = g8 >> 1;               // k-half for A matrices
    int aRow8 = (g8 & 1) * 8;          // +8 rows for m-hi matrices
    int bHalf = g8 & 1;                // k-half for B matrices
    int bRow8 = (g8 >> 1) * 8;         // +8 rows for n-hi matrices
    uint32_t aTerm[4], bTerm[2];
#pragma unroll
    for (int mt = 0; mt < 4; mt++) {
        int row = wm * 64 + mt * 16 + aRow8 + lr;
        aTerm[mt] = sb + SMEM_CTRL + row * 128;
    }
#pragma unroll
    for (int ntp = 0; ntp < 2; ntp++) {
        int row = wn * 32 + ntp * 16 + bRow8 + lr;
        bTerm[ntp] = sb + SMEM_CTRL + 16384 + row * 128;
    }

    FILL1(0); FILL1(1);
    for (int c = 0; c < NCH1; c++) {
        if (c + 1 < NCH1) asm volatile("cp.async.wait_group 1;" ::: "memory");
        else              asm volatile("cp.async.wait_group 0;" ::: "memory");
        __syncthreads();
        if (c + 2 < NCH1) FILL1(c + 2);       // overwrites stage consumed at c-1
        uint32_t so = (uint32_t)(c % NSTAGE) * STAGE_BYTES;
#pragma unroll
        for (int ks = 0; ks < 4; ks++) {           // k16 per step, 4 steps = 64
            uint32_t aoff = so + ((((uint32_t)(ks * 2 + aHalf)) << 4) ^ rx);
            uint32_t boff = so + ((((uint32_t)(ks * 2 + bHalf)) << 4) ^ rx);
            uint32_t a[4][4], b[4][2];
#pragma unroll
            for (int mt = 0; mt < 4; mt++) ldsm4(a[mt], aTerm[mt] + aoff);
#pragma unroll
            for (int ntp = 0; ntp < 2; ntp++) {
                uint32_t bb[4];
                ldsm4(bb, bTerm[ntp] + boff);
                b[2 * ntp][0] = bb[0]; b[2 * ntp][1] = bb[1];
                b[2 * ntp + 1][0] = bb[2]; b[2 * ntp + 1][1] = bb[3];
            }
#pragma unroll
            for (int mt = 0; mt < 4; mt++)
#pragma unroll
                for (int nt = 0; nt < 4; nt++)
                    mma_f16(acc[mt][nt], a[mt][0], a[mt][1], a[mt][2], a[mt][3],
                            b[nt][0], b[nt][1]);
        }
    }

    // epilogue: act = fp16(silu(h1)*h2), in registers
#pragma unroll
    for (int mt = 0; mt < 4; mt++) {
        int r0 = wm * 64 + mt * 16 + g;
        int s0 = rs[r0], s1 = rs[r0 + 8];
#pragma unroll
        for (int nt = 0; nt < 4; nt++) {
            int col = n0p + wn * 16 + nt * 4 + tg;
            if (s0 >= 0) {
                float h1 = acc[mt][nt][0], h2 = acc[mt][nt][1];
                float v = h1 / (1.f + __expf(-h1)) * h2;
                g_act[(size_t)s0 * DFF + col] = __float2half_rn(v);
            }
            if (s1 >= 0) {
                float h1 = acc[mt][nt][2], h2 = acc[mt][nt][3];
                float v = h1 / (1.f + __expf(-h1)) * h2;
                g_act[(size_t)s1 * DFF + col] = __float2half_rn(v);
            }
        }
    }
#undef FILL1
}

// ---------------- gemm2: y = act @ w_out^T -> g_y ----------------
__global__ void __launch_bounds__(256, 2) gemm2_mma(const __half* __restrict__ w2r) {
    extern __shared__ char sm[];
    int e = blockIdx.z;
    int cnt = g_counts[e];
    int m0 = blockIdx.y * 128;
    if (m0 >= cnt) return;
    int n0 = blockIdx.x * 128;
    int tid = threadIdx.x, lane = tid & 31, wid = tid >> 5;
    int g = lane >> 2, tg = lane & 3;
    int wm = wid & 1, wn = wid >> 1;

    int* rs = (int*)sm;
    const __half** rowp = (const __half**)(sm + 512);
    if (tid < 128) {
        int m = m0 + tid;
        int slot = (m < cnt) ? g_slots[e * T_TOK + m] : -1;
        rs[tid] = slot;
        rowp[tid] = (slot >= 0) ? (g_act + (size_t)slot * DFF) : g_act;
    }
    __syncthreads();

    uint32_t sb = smem_u32(sm);
    int seg = tid & 7;
    const __half* pA[4]; uint32_t dA[4];
    const __half* pB[4]; uint32_t dB[4];
#pragma unroll
    for (int i = 0; i < 4; i++) {
        int row = i * 32 + (tid >> 3);
        pA[i] = rowp[row] + seg * 8;
        dA[i] = SMEM_CTRL + row * 128 + (((seg ^ (row & 7)) & 7) << 4);
        pB[i] = w2r + ((size_t)e * DM + n0 + row) * DFF + seg * 8;
        dB[i] = SMEM_CTRL + 16384 + row * 128 + (((seg ^ (row & 7)) & 7) << 4);
    }

#define FILL2(c_) do { \
        uint32_t so_ = (uint32_t)((c_) % NSTAGE) * STAGE_BYTES; \
        _Pragma("unroll") \
        for (int i = 0; i < 4; i++) { \
            cp16(sb + dA[i] + so_, pA[i]); pA[i] += KC; \
            cp16(sb + dB[i] + so_, pB[i]); pB[i] += KC; \
        } \
        CP_COMMIT(); \
    } while (0)

    float acc[4][4][4];
#pragma unroll
    for (int mt = 0; mt < 4; mt++)
#pragma unroll
        for (int nt = 0; nt < 4; nt++)
#pragma unroll
            for (int r = 0; r < 4; r++) acc[mt][nt][r] = 0.f;

    int g8 = lane >> 3, lr = lane & 7;
    uint32_t rx = (uint32_t)lr << 4;
    int aHalf = g8 >> 1;
    int aRow8 = (g8 & 1) * 8;
    int bHalf = g8 & 1;
    int bRow8 = (g8 >> 1) * 8;
    uint32_t aTerm[4], bTerm[2];
#pragma unroll
    for (int mt = 0; mt < 4; mt++) {
        int row = wm * 64 + mt * 16 + aRow8 + lr;
        aTerm[mt] = sb + SMEM_CTRL + row * 128;
    }
#pragma unroll
    for (int ntp = 0; ntp < 2; ntp++) {
        int row = wn * 32 + ntp * 16 + bRow8 + lr;
        bTerm[ntp] = sb + SMEM_CTRL + 16384 + row * 128;
    }

    FILL2(0); FILL2(1);
    for (int c = 0; c < NCH2; c++) {
        if (c + 1 < NCH2) asm volatile("cp.async.wait_group 1;" ::: "memory");
        else              asm volatile("cp.async.wait_group 0;" ::: "memory");
        __syncthreads();
        if (c + 2 < NCH2) FILL2(c + 2);
        uint32_t so = (uint32_t)(c % NSTAGE) * STAGE_BYTES;
#pragma unroll
        for (int ks = 0; ks < 4; ks++) {
            uint32_t aoff = so + ((((uint32_t)(ks * 2 + aHalf)) << 4) ^ rx);
            uint32_t boff = so + ((((uint32_t)(ks * 2 + bHalf)) << 4) ^ rx);
            uint32_t a[4][4], b[4][2];
#pragma unroll
            for (int mt = 0; mt < 4; mt++) ldsm4(a[mt], aTerm[mt] + aoff);
#pragma unroll
            for (int ntp = 0; ntp < 2; ntp++) {
                uint32_t bb[4];
                ldsm4(bb, bTerm[ntp] + boff);
                b[2 * ntp][0] = bb[0]; b[2 * ntp][1] = bb[1];
                b[2 * ntp + 1][0] = bb[2]; b[2 * ntp + 1][1] = bb[3];
            }
#pragma unroll
            for (int mt = 0; mt < 4; mt++)
#pragma unroll
                for (int nt = 0; nt < 4; nt++)
                    mma_f16(acc[mt][nt], a[mt][0], a[mt][1], a[mt][2], a[mt][3],
                            b[nt][0], b[nt][1]);
        }
    }

#pragma unroll
    for (int mt = 0; mt < 4; mt++) {
        int r0 = wm * 64 + mt * 16 + g;
        int s0 = rs[r0], s1 = rs[r0 + 8];
#pragma unroll
        for (int nt = 0; nt < 4; nt++) {
            int col = n0 + wn * 32 + nt * 8 + tg * 2;
            if (s0 >= 0) {
                float2 v = make_float2(acc[mt][nt][0], acc[mt][nt][1]);
                *(float2*)(g_y + (size_t)s0 * DM + col) = v;
            }
            if (s1 >= 0) {
                float2 v = make_float2(acc[mt][nt][2], acc[mt][nt][3]);
                *(float2*)(g_y + (size_t)s1 * DM + col) = v;
            }
        }
    }
#undef FILL2
}

// ---------------- combine: out[t] = g0*y[2t] + g1*y[2t+1] ----------------
__global__ void __launch_bounds__(256) combine_kernel(float* __restrict__ out) {
    int i = blockIdx.x * 256 + threadIdx.x;    // float4 index
    int t = i >> 8;
    int f = (i & 255) * 4;
    float g0 = g_top_gate[t * 2 + 0];
    float g1 = g_top_gate[t * 2 + 1];
    float4 a = *(const float4*)(g_y + (size_t)(t * 2 + 0) * DM + f);
    float4 b = *(const float4*)(g_y + (size_t)(t * 2 + 1) * DM + f);
    float4 o;
    o.x = g0 * a.x + g1 * b.x;
    o.y = g0 * a.y + g1 * b.y;
    o.z = g0 * a.z + g1 * b.z;
    o.w = g0 * a.w + g1 * b.w;
    *(float4*)(out + (size_t)t * DM + f) = o;
}

// ---------------- launcher ----------------
extern "C" void kernel_launch(void* const* d_in, const int* in_sizes, int n_in,
                              void* d_out, int out_size) {
    const float* x    = (const float*)d_in[0];   // [4096, 1024]
    const float* rw   = (const float*)d_in[1];   // [8, 1024]
    const float* w_in = (const float*)d_in[2];   // [8, 4096, 1024]
    const float* wout = (const float*)d_in[3];   // [8, 1024, 2048]
    float* out    = (float*)d_out;               // [4096, 1024]
    float* logits = out + (size_t)T_TOK * DM;    // [4096, 8]

    cudaFuncSetAttribute(gemm1_mma, cudaFuncAttributeMaxDynamicSharedMemorySize, SMEM_TOTAL_G);
    cudaFuncSetAttribute(gemm2_mma, cudaFuncAttributeMaxDynamicSharedMemorySize, SMEM_TOTAL_G);

    __half* xr;  cudaGetSymbolAddress((void**)&xr,  g_xr);
    __half* w1r; cudaGetSymbolAddress((void**)&w1r, g_w1r);
    __half* w2r; cudaGetSymbolAddress((void**)&w2r, g_w2r);

    int nx = T_TOK * DM / 4;
    int n1 = NEXP * DFF2 * DM / 4;
    int n2 = NEXP * DM * DFF / 4;
    int ntot = nx + n1 + n2;

    init_kernel<<<1, 32>>>();
    round_all_kernel<<<(ntot / 4 + 255) / 256, 256>>>(
        (const float4*)x, (uint2*)xr, nx,
        (const float4*)w_in, (uint2*)w1r, n1,
        (const float4*)wout, (uint2*)w2r, n2);
    router_kernel<<<T_TOK, 256>>>(x, rw, logits);
    bin_kernel<<<(T_TOK * 2 + 255) / 256, 256>>>();
    gemm1_mma<<<dim3(DFF / 64, T_TOK / 128, NEXP), 256, SMEM_TOTAL_G>>>(w1r);
    gemm2_mma<<<dim3(DM / 128, T_TOK / 128, NEXP), 256, SMEM_TOTAL_G>>>(w2r);
    combine_kernel<<<T_TOK * DM / 4 / 256, 256>>>(out);
}